// round 14
// baseline (speedup 1.0000x reference)
#include <cuda_runtime.h>
#include <cuda_bf16.h>
#include <cstdint>

// ---------------------------------------------------------------------------
// Mobile2Former cross-attention, single-pass streaming softmax (scores bounded
// |s| < ~2; softmax shift-invariant so no max subtraction needed).
//
//   x : (64, 96, 112, 112) fp32 -> xf (b, n=12544, c=96), K = V = xf
//   q = SCALE * (z @ Wq + bq); p = exp(q.xf); out = (p@xf)/sum(p)
//   y = z + out @ Wo + bo
//
// Launch order: marker, qproj, marker, attn, combine, proj
//   (ncu captures absolute launch index 3 -> attn)
//
// attn (R14 = R13 with the tile PAIR split across two warp-groups):
//   256 threads, 2 CTAs/SM -> 4 warps/SMSP (was 3). Warp w -> role (w&3),
//   tile-parity (w>>2). Same tf32 mma bodies as R13 on ONE tile per warp.
//   Per-work smem traffic unchanged (+~7% q loads); +33% issue slots.
//   Epilogue: parity-1 warps stage Oacc via smem; parity-0 add + store.
// ---------------------------------------------------------------------------

#define BATCH   64
#define CHN     96
#define HWN     12544
#define NSPLIT  14
#define CHUNK   896
#define NHM     24
#define TN      64
#define TNP     68             // padded row stride (floats)
#define NTILES  14
#define NPAIRS  7
#define THREADS2 256
#define XS_FLOATS (CHN * TNP)                 // 6528 per buffer
#define PS_FLOATS (NHM * TNP)                 // 1632 per tile
#define QA_U32   (12 * 32 * 4)                // 1536
#define QB_U32   (12 * 32 * 2)                // 768
#define SMEM2_FLOATS (2*XS_FLOATS + 2*PS_FLOATS + QA_U32 + QB_U32 + 224)  // 18848
#define SMEM2_BYTES  (SMEM2_FLOATS * 4)       // 75392 B (2 CTAs/SM)
#define SCALE_F 0.10206207261596575f          // 96^-0.5
#define QSPLIT  4

__device__ float g_Qp[QSPLIT][BATCH * NHM * CHN];        // K-split q partials
__device__ float g_accP[BATCH * NSPLIT * NHM * CHN];     // split numerators
__device__ float g_LP[BATCH * NSPLIT * NHM];             // split denominators
__device__ float g_O[BATCH * 6 * 384];                   // attn out [b][m][h*96+c]

// ---- tf32 helpers ----
__device__ __forceinline__ uint32_t f2tf(float f) {
    uint32_t u;
    asm("cvt.rna.tf32.f32 %0, %1;" : "=r"(u) : "f"(f));
    return u;
}
__device__ __forceinline__ void mma8(float* c,
                                     uint32_t a0, uint32_t a1, uint32_t a2, uint32_t a3,
                                     uint32_t b0, uint32_t b1) {
    asm("mma.sync.aligned.m16n8k8.row.col.f32.tf32.tf32.f32 "
        "{%0,%1,%2,%3}, {%4,%5,%6,%7}, {%8,%9}, {%0,%1,%2,%3};"
        : "+f"(c[0]), "+f"(c[1]), "+f"(c[2]), "+f"(c[3])
        : "r"(a0), "r"(a1), "r"(a2), "r"(a3), "r"(b0), "r"(b1));
}
__device__ __forceinline__ void cp_async16(uint32_t dst, const float* src) {
    asm volatile("cp.async.cg.shared.global [%0], [%1], 16;" :: "r"(dst), "l"(src));
}

__global__ void prof_marker() {}

// ---------------------------------------------------------------------------
// Kernel 1: Q projection, grid (BATCH, 4): grid.y = K-quarter (48 d each).
// ---------------------------------------------------------------------------
__global__ __launch_bounds__(384)
void qproj_kernel(const float* __restrict__ z,
                  const float* __restrict__ Wq,
                  const float* __restrict__ bq) {
    __shared__ float zs[6 * 192];
    const int b = blockIdx.x;
    const int part = blockIdx.y;
    const int j = threadIdx.x;
    for (int i = j; i < 6 * 192; i += 384) zs[i] = z[b * 6 * 192 + i];
    __syncthreads();

    const int d0 = 48 * part;
    float acc[6] = {0.f, 0.f, 0.f, 0.f, 0.f, 0.f};
    #pragma unroll 16
    for (int dd = 0; dd < 48; dd++) {
        const float w = Wq[(d0 + dd) * 384 + j];
        #pragma unroll
        for (int m = 0; m < 6; m++) acc[m] += zs[m * 192 + d0 + dd] * w;
    }
    const int h = j / CHN, c = j % CHN;
    const float bias = (part == 0) ? bq[j] : 0.f;
    #pragma unroll
    for (int m = 0; m < 6; m++)
        g_Qp[part][(size_t)b * (NHM * CHN) + (h * 6 + m) * CHN + c] =
            (acc[m] + bias) * SCALE_F;
}

// ---------------------------------------------------------------------------
// Kernel 2: streaming attention, tf32 tensor cores, pair split across warps.
// ---------------------------------------------------------------------------
__global__ __launch_bounds__(THREADS2, 2)
void attn_kernel(const float* __restrict__ x) {
    extern __shared__ float sm[];
    float*    Xs0  = sm;                                   // [2][96][68]
    float*    PsA  = sm + 2 * XS_FLOATS;                   // [24][68]
    float*    PsB  = PsA + PS_FLOATS;                      // [24][68]
    uint4*    qA   = (uint4*)(PsB + PS_FLOATS);            // [12][32]
    uint2*    qB   = (uint2*)((uint32_t*)qA + QA_U32);     // [12][32]
    float*    Lred = (float*)((uint32_t*)qA + QA_U32 + QB_U32);  // [8][24]

    const int t     = threadIdx.x;
    const int b     = blockIdx.y;
    const int split = blockIdx.x;
    const int lane  = t & 31;
    const int w     = t >> 5;        // warp 0..7
    const int w03   = w & 3;         // role within parity group
    const int tp    = w >> 2;        // tile parity (0 -> bufA, 1 -> bufB)
    const int gid   = lane >> 2;     // 0..7
    const int tig   = lane & 3;      // 0..3

    // ---- stage Q (coalesced) into Xs0, then build deduped tf32 fragments ----
    {
        const size_t qb0 = (size_t)b * (NHM * CHN);
        for (int i = t; i < NHM * CHN; i += THREADS2)
            Xs0[i] = g_Qp[0][qb0 + i] + g_Qp[1][qb0 + i]
                   + g_Qp[2][qb0 + i] + g_Qp[3][qb0 + i];
        __syncthreads();
        // rows gid, 8+gid, 16+gid x cols (k*8+tig, +4): 6 unique u32/lane/k
        for (int k = w; k < 12; k += 8) {
            const int c0 = k * 8 + tig;
            const uint32_t q0 = f2tf(Xs0[gid * 96 + c0]);
            const uint32_t q1 = f2tf(Xs0[(8 + gid) * 96 + c0]);
            const uint32_t q2 = f2tf(Xs0[(16 + gid) * 96 + c0]);
            const uint32_t q3 = f2tf(Xs0[gid * 96 + c0 + 4]);
            const uint32_t q4 = f2tf(Xs0[(8 + gid) * 96 + c0 + 4]);
            const uint32_t q5 = f2tf(Xs0[(16 + gid) * 96 + c0 + 4]);
            qA[k * 32 + lane] = make_uint4(q0, q1, q3, q4);
            qB[k * 32 + lane] = make_uint2(q2, q5);
        }
        __syncthreads();
    }

    float Oacc[2][3][4];            // [mtile][c-tile][frag] (this parity's tiles)
    float Lp[3] = {0.f, 0.f, 0.f};  // exp sums: hm = gid, 8+gid, 16+gid
    #pragma unroll
    for (int a = 0; a < 2; a++)
        #pragma unroll
        for (int ct = 0; ct < 3; ct++)
            #pragma unroll
            for (int i = 0; i < 4; i++) Oacc[a][ct][i] = 0.f;

    const float* xb = x + (size_t)b * CHN * HWN;
    const int n0 = split * CHUNK;
    const int n0w = 16 * w03;     // GEMM1: warp's n-quarter
    const int c0w = 24 * w03;     // GEMM2: warp's c-quarter

    const float* XsW = Xs0 + tp * XS_FLOATS;     // this warp's tile buffer
    float*       PsW = tp ? PsB : PsA;           // this warp's P buffer

    auto prefetch = [&](int buf, int tile) {
        const int base = n0 + tile * TN;
        uint32_t dst = (uint32_t)__cvta_generic_to_shared(Xs0 + buf * XS_FLOATS);
        #pragma unroll
        for (int kk = 0; kk < 6; kk++) {
            const int idx = kk * THREADS2 + t;
            const int c = idx >> 4, f4 = (idx & 15) << 2;
            cp_async16(dst + (uint32_t)(c * TNP + f4) * 4,
                       xb + (size_t)c * HWN + base + f4);
        }
        asm volatile("cp.async.commit_group;");
    };

    prefetch(0, 0);
    prefetch(1, 1);

    for (int r = 0; r < NPAIRS; r++) {
        asm volatile("cp.async.wait_group 0;");   // both tiles of the pair
        __syncthreads();

        // ---- GEMM1: scores for THIS warp's tile, its n-quarter ----
        float c4[2][2][4];
        #pragma unroll
        for (int a = 0; a < 2; a++)
            #pragma unroll
            for (int nt = 0; nt < 2; nt++)
                #pragma unroll
                for (int i = 0; i < 4; i++) c4[a][nt][i] = 0.f;

        #pragma unroll
        for (int k = 0; k < 12; k++) {
            const uint4 fa = qA[k * 32 + lane];
            const uint2 fb = qB[k * 32 + lane];
            // af0 = {fa.x, fa.y, fa.z, fa.w}; af1 = {fa.y, fb.x, fa.w, fb.y}
            #pragma unroll
            for (int nt = 0; nt < 2; nt++) {
                const int ncol = n0w + nt * 8 + gid;
                const uint32_t b0 = f2tf(XsW[(k * 8 + tig) * TNP + ncol]);
                const uint32_t b1 = f2tf(XsW[(k * 8 + tig + 4) * TNP + ncol]);
                mma8(c4[0][nt], fa.x, fa.y, fa.z, fa.w, b0, b1);
                mma8(c4[1][nt], fa.y, fb.x, fa.w, fb.y, b0, b1);
            }
        }

        // ---- exp -> PsW (tf32-rounded) + L ----
        #pragma unroll
        for (int nt = 0; nt < 2; nt++) {
            const int col = n0w + nt * 8 + 2 * tig;
            {
                const float p0 = __uint_as_float(f2tf(__expf(c4[0][nt][0])));
                const float p1 = __uint_as_float(f2tf(__expf(c4[0][nt][1])));
                PsW[gid * TNP + col] = p0; PsW[gid * TNP + col + 1] = p1;
                Lp[0] += p0 + p1;
            }
            {
                const float p0 = __uint_as_float(f2tf(__expf(c4[0][nt][2])));
                const float p1 = __uint_as_float(f2tf(__expf(c4[0][nt][3])));
                PsW[(8 + gid) * TNP + col] = p0; PsW[(8 + gid) * TNP + col + 1] = p1;
                Lp[1] += p0 + p1;
            }
            {
                const float p0 = __uint_as_float(f2tf(__expf(c4[1][nt][2])));
                const float p1 = __uint_as_float(f2tf(__expf(c4[1][nt][3])));
                PsW[(16 + gid) * TNP + col] = p0; PsW[(16 + gid) * TNP + col + 1] = p1;
                Lp[2] += p0 + p1;
            }
        }
        __syncthreads();     // full Ps of both tiles visible

        // ---- GEMM2: THIS warp's tile, its c-quarter ----
        #pragma unroll
        for (int k = 0; k < 8; k++) {
            const int nc = k * 8 + tig;
            const uint32_t pa0 = __float_as_uint(PsW[gid * TNP + nc]);
            const uint32_t pa1 = __float_as_uint(PsW[(8 + gid) * TNP + nc]);
            const uint32_t pa2 = __float_as_uint(PsW[gid * TNP + nc + 4]);
            const uint32_t pa3 = __float_as_uint(PsW[(8 + gid) * TNP + nc + 4]);
            const uint32_t pb1 = __float_as_uint(PsW[(16 + gid) * TNP + nc]);
            const uint32_t pb3 = __float_as_uint(PsW[(16 + gid) * TNP + nc + 4]);
            #pragma unroll
            for (int ct = 0; ct < 3; ct++) {
                const int crow = c0w + ct * 8 + gid;
                const uint32_t b0 = f2tf(XsW[crow * TNP + nc]);
                const uint32_t b1 = f2tf(XsW[crow * TNP + nc + 4]);
                mma8(Oacc[0][ct], pa0, pa1, pa2, pa3, b0, b1);   // rows 0-15
                mma8(Oacc[1][ct], pa1, pb1, pa3, pb3, b0, b1);   // rows 8-23
            }
        }
        __syncthreads();     // close Xs/Ps reads before refill/rewrite
        if (r + 1 < NPAIRS) {
            prefetch(0, 2 * r + 2);
            prefetch(1, 2 * r + 3);
        }
    }

    // ---- cross-parity Oacc combine: tp=1 warps stage into Xs0, tp=0 add ----
    // (all reads of Xs0 closed by the final barrier above)
    if (tp == 1) {
        float* st = Xs0 + w03 * 768;
        #pragma unroll
        for (int a = 0; a < 2; a++)
            #pragma unroll
            for (int ct = 0; ct < 3; ct++)
                #pragma unroll
                for (int i = 0; i < 4; i++)
                    st[((a * 3 + ct) * 4 + i) * 32 + lane] = Oacc[a][ct][i];
    }
    __syncthreads();
    const size_t outbase = (size_t)(b * NSPLIT + split) * (NHM * CHN);
    if (tp == 0) {
        const float* st = Xs0 + w03 * 768;
        float of[2][3][4];
        #pragma unroll
        for (int a = 0; a < 2; a++)
            #pragma unroll
            for (int ct = 0; ct < 3; ct++)
                #pragma unroll
                for (int i = 0; i < 4; i++)
                    of[a][ct][i] = Oacc[a][ct][i] +
                                   st[((a * 3 + ct) * 4 + i) * 32 + lane];
        #pragma unroll
        for (int ct = 0; ct < 3; ct++) {
            const int col = c0w + ct * 8 + 2 * tig;
            g_accP[outbase + gid * CHN + col]            = of[0][ct][0];
            g_accP[outbase + gid * CHN + col + 1]        = of[0][ct][1];
            g_accP[outbase + (8 + gid) * CHN + col]      = of[0][ct][2];
            g_accP[outbase + (8 + gid) * CHN + col + 1]  = of[0][ct][3];
            g_accP[outbase + (16 + gid) * CHN + col]     = of[1][ct][2];
            g_accP[outbase + (16 + gid) * CHN + col + 1] = of[1][ct][3];
        }
    }

    // ---- L reduction: sum over tig lanes, then over the 8 warps ----
    #pragma unroll
    for (int i = 0; i < 3; i++) {
        float v = Lp[i];
        v += __shfl_xor_sync(0xffffffffu, v, 1);
        v += __shfl_xor_sync(0xffffffffu, v, 2);
        Lp[i] = v;
    }
    if (tig == 0) {
        Lred[w * 24 + gid]      = Lp[0];
        Lred[w * 24 + 8 + gid]  = Lp[1];
        Lred[w * 24 + 16 + gid] = Lp[2];
    }
    __syncthreads();
    if (t < NHM) {
        float v = 0.f;
        #pragma unroll
        for (int i = 0; i < 8; i++) v += Lred[i * 24 + t];
        g_LP[(b * NSPLIT + split) * NHM + t] = v;
    }
}

// ---------------------------------------------------------------------------
// Kernel 3: combine split partials -> g_O[b][m][h*96+c] = (sum_s acc)/(sum_s L)
// ---------------------------------------------------------------------------
__global__ __launch_bounds__(256)
void combine_kernel() {
    const int i = blockIdx.x * 256 + threadIdx.x;   // 0 .. 147455
    const int b = i / (NHM * CHN);
    const int r = i % (NHM * CHN);
    const int hm = r / CHN, c = r % CHN;
    float a = 0.f, L = 0.f;
    #pragma unroll
    for (int s = 0; s < NSPLIT; s++) {
        a += g_accP[(size_t)(b * NSPLIT + s) * (NHM * CHN) + r];
        L += g_LP[(b * NSPLIT + s) * NHM + hm];
    }
    const int h = hm / 6, m = hm % 6;
    g_O[(size_t)b * 2304 + m * 384 + h * CHN + c] = a / L;
}

// ---------------------------------------------------------------------------
// Kernel 4: output projection + residual (d = t % 192; NOT a bitmask).
// ---------------------------------------------------------------------------
__global__ __launch_bounds__(384)
void proj_kernel(const float* __restrict__ z,
                 const float* __restrict__ Wo,
                 const float* __restrict__ bo,
                 float* __restrict__ out) {
    __shared__ float outRow[6 * 384];
    __shared__ float part[192 * 6];
    const int b = blockIdx.x;
    const int t = threadIdx.x;
    const int d = t % 192;

    for (int i = t; i < 2304; i += 384) outRow[i] = g_O[(size_t)b * 2304 + i];
    __syncthreads();

    const int j0 = (t >= 192) ? 192 : 0;
    float accm[6] = {0.f, 0.f, 0.f, 0.f, 0.f, 0.f};
    #pragma unroll 16
    for (int jj = 0; jj < 192; jj++) {
        const int j = j0 + jj;
        const float w = Wo[j * 192 + d];
        #pragma unroll
        for (int m = 0; m < 6; m++) accm[m] += outRow[m * 384 + j] * w;
    }
    if (t >= 192) {
        #pragma unroll
        for (int m = 0; m < 6; m++) part[d * 6 + m] = accm[m];
    }
    __syncthreads();
    if (t < 192) {
        const float bod = bo[d];
        #pragma unroll
        for (int m = 0; m < 6; m++)
            out[((size_t)b * 6 + m) * 192 + d] =
                z[((size_t)b * 6 + m) * 192 + d] + accm[m] + part[d * 6 + m] + bod;
    }
}

// ---------------------------------------------------------------------------
extern "C" void kernel_launch(void* const* d_in, const int* in_sizes, int n_in,
                              void* d_out, int out_size) {
    const float* x  = (const float*)d_in[0];
    const float* z  = (const float*)d_in[1];
    const float* Wq = (const float*)d_in[2];
    const float* bq = (const float*)d_in[3];
    const float* Wo = (const float*)d_in[4];
    const float* bo = (const float*)d_in[5];
    float* out = (float*)d_out;

    cudaFuncSetAttribute(attn_kernel,
                         cudaFuncAttributeMaxDynamicSharedMemorySize, SMEM2_BYTES);

    prof_marker<<<1, 32>>>();                                   // idx 0
    qproj_kernel<<<dim3(BATCH, QSPLIT), 384>>>(z, Wq, bq);      // idx 1
    prof_marker<<<1, 32>>>();                                   // idx 2
    attn_kernel<<<dim3(NSPLIT, BATCH), THREADS2, SMEM2_BYTES>>>(x);  // idx 3 (ncu)
    combine_kernel<<<576, 256>>>();                             // idx 4
    proj_kernel<<<BATCH, 384>>>(z, Wo, bo, out);                // idx 5
}

// round 15
// speedup vs baseline: 1.0033x; 1.0033x over previous
#include <cuda_runtime.h>
#include <cuda_bf16.h>
#include <cstdint>

// ---------------------------------------------------------------------------
// Mobile2Former cross-attention, single-pass streaming softmax (scores bounded
// |s| < ~2; softmax shift-invariant so no max subtraction needed).
//
//   x : (64, 96, 112, 112) fp32 -> xf (b, n=12544, c=96), K = V = xf
//   q = SCALE * (z @ Wq + bq); p = exp(q.xf); out = (p@xf)/sum(p)
//   y = z + out @ Wo + bo
//
// Launch order: marker, qproj, marker, attn, combine, proj
//   (ncu captures absolute launch index 3 -> attn)
//
// attn (R15 = R13 with cp.async.bulk tile loads):
//   Per-thread cp.async (1536 LDGSTS/tile, rt~8cyc each = the hidden issue
//   cost) replaced by 96 row-wise cp.async.bulk copies (256B each) completing
//   on an mbarrier (expect_tx = 24576). Issue ops/round: 3072 -> 192.
//   Pipeline: wait(mbarA)+wait(mbarB); expect_tx(next phase); bar;
//   GEMM1(pair)+exp; bar; GEMM2(A); bar; bulk(bufA); GEMM2(B); bar; bulk(bufB).
//   tf32 mma bodies, qfrag dedup, epilogue: R13 verbatim. 128 thr, 3 CTAs/SM.
// ---------------------------------------------------------------------------

#define BATCH   64
#define CHN     96
#define HWN     12544
#define NSPLIT  14
#define CHUNK   896
#define NHM     24
#define TN      64
#define TNP     68             // padded row stride (floats)
#define NTILES  14
#define NPAIRS  7
#define THREADS2 128
#define XS_FLOATS (CHN * TNP)                 // 6528 per buffer
#define PS_FLOATS (NHM * TNP)                 // 1632 per tile
#define QA_U32   (12 * 32 * 4)                // 1536
#define QB_U32   (12 * 32 * 2)                // 768
#define LRED_OFF (2*XS_FLOATS + 2*PS_FLOATS + QA_U32 + QB_U32)   // 18624
#define MBAR_OFF (LRED_OFF + 96)                                  // 18720 (8B-aligned)
#define SMEM2_FLOATS (MBAR_OFF + 8)           // 18728
#define SMEM2_BYTES  (SMEM2_FLOATS * 4)       // 74912 B (3 CTAs/SM)
#define TILE_BYTES_TX 24576u                  // 96 rows * 256 B
#define SCALE_F 0.10206207261596575f          // 96^-0.5
#define QSPLIT  4

__device__ float g_Qp[QSPLIT][BATCH * NHM * CHN];        // K-split q partials
__device__ float g_accP[BATCH * NSPLIT * NHM * CHN];     // split numerators
__device__ float g_LP[BATCH * NSPLIT * NHM];             // split denominators
__device__ float g_O[BATCH * 6 * 384];                   // attn out [b][m][h*96+c]

// ---- tf32 helpers ----
__device__ __forceinline__ uint32_t f2tf(float f) {
    uint32_t u;
    asm("cvt.rna.tf32.f32 %0, %1;" : "=r"(u) : "f"(f));
    return u;
}
__device__ __forceinline__ void mma8(float* c,
                                     uint32_t a0, uint32_t a1, uint32_t a2, uint32_t a3,
                                     uint32_t b0, uint32_t b1) {
    asm("mma.sync.aligned.m16n8k8.row.col.f32.tf32.tf32.f32 "
        "{%0,%1,%2,%3}, {%4,%5,%6,%7}, {%8,%9}, {%0,%1,%2,%3};"
        : "+f"(c[0]), "+f"(c[1]), "+f"(c[2]), "+f"(c[3])
        : "r"(a0), "r"(a1), "r"(a2), "r"(a3), "r"(b0), "r"(b1));
}

// ---- mbarrier / bulk-copy helpers ----
__device__ __forceinline__ void mbar_init(uint32_t mbar, uint32_t count) {
    asm volatile("mbarrier.init.shared::cta.b64 [%0], %1;"
                 :: "r"(mbar), "r"(count) : "memory");
}
__device__ __forceinline__ void mbar_expect(uint32_t mbar, uint32_t bytes) {
    asm volatile("mbarrier.arrive.expect_tx.shared::cta.b64 _, [%0], %1;"
                 :: "r"(mbar), "r"(bytes) : "memory");
}
__device__ __forceinline__ void mbar_wait(uint32_t mbar, uint32_t parity) {
    asm volatile(
        "{\n\t.reg .pred P;\n"
        "LW_%=:\n\t"
        "mbarrier.try_wait.parity.acquire.cta.shared::cta.b64 P, [%0], %1, 0x989680;\n\t"
        "@P bra LD_%=;\n\t"
        "bra LW_%=;\n"
        "LD_%=:\n\t}"
        :: "r"(mbar), "r"(parity) : "memory");
}
__device__ __forceinline__ void cp_bulk(uint32_t dst, const float* src,
                                        uint32_t bytes, uint32_t mbar) {
    asm volatile(
        "cp.async.bulk.shared::cta.global.mbarrier::complete_tx::bytes "
        "[%0], [%1], %2, [%3];"
        :: "r"(dst), "l"(src), "r"(bytes), "r"(mbar) : "memory");
}

__global__ void prof_marker() {}

// ---------------------------------------------------------------------------
// Kernel 1: Q projection, grid (BATCH, 4): grid.y = K-quarter (48 d each).
// ---------------------------------------------------------------------------
__global__ __launch_bounds__(384)
void qproj_kernel(const float* __restrict__ z,
                  const float* __restrict__ Wq,
                  const float* __restrict__ bq) {
    __shared__ float zs[6 * 192];
    const int b = blockIdx.x;
    const int part = blockIdx.y;
    const int j = threadIdx.x;
    for (int i = j; i < 6 * 192; i += 384) zs[i] = z[b * 6 * 192 + i];
    __syncthreads();

    const int d0 = 48 * part;
    float acc[6] = {0.f, 0.f, 0.f, 0.f, 0.f, 0.f};
    #pragma unroll 16
    for (int dd = 0; dd < 48; dd++) {
        const float w = Wq[(d0 + dd) * 384 + j];
        #pragma unroll
        for (int m = 0; m < 6; m++) acc[m] += zs[m * 192 + d0 + dd] * w;
    }
    const int h = j / CHN, c = j % CHN;
    const float bias = (part == 0) ? bq[j] : 0.f;
    #pragma unroll
    for (int m = 0; m < 6; m++)
        g_Qp[part][(size_t)b * (NHM * CHN) + (h * 6 + m) * CHN + c] =
            (acc[m] + bias) * SCALE_F;
}

// ---------------------------------------------------------------------------
// Kernel 2: streaming attention, tf32 tensor cores, bulk-copy loads.
// ---------------------------------------------------------------------------
__global__ __launch_bounds__(THREADS2, 3)
void attn_kernel(const float* __restrict__ x) {
    extern __shared__ float sm[];
    float*    Xs0  = sm;                                   // [2][96][68]
    float*    PsA  = sm + 2 * XS_FLOATS;                   // [24][68]
    float*    PsB  = PsA + PS_FLOATS;                      // [24][68]
    uint4*    qA   = (uint4*)(PsB + PS_FLOATS);            // [12][32]
    uint2*    qB   = (uint2*)((uint32_t*)qA + QA_U32);     // [12][32]
    float*    Lred = sm + LRED_OFF;                        // [4][24]

    const uint32_t sbase = (uint32_t)__cvta_generic_to_shared(sm);
    const uint32_t mbarA = sbase + MBAR_OFF * 4;
    const uint32_t mbarB = mbarA + 8;

    const int t     = threadIdx.x;
    const int b     = blockIdx.y;
    const int split = blockIdx.x;
    const int lane  = t & 31;
    const int w     = t >> 5;
    const int gid   = lane >> 2;     // 0..7
    const int tig   = lane & 3;      // 0..3

    if (t == 0) {
        mbar_init(mbarA, 1);
        mbar_init(mbarB, 1);
        asm volatile("fence.proxy.async.shared::cta;" ::: "memory");
    }

    // ---- stage Q (coalesced) into Xs0, then build deduped tf32 fragments ----
    {
        const size_t qb0 = (size_t)b * (NHM * CHN);
        for (int i = t; i < NHM * CHN; i += THREADS2)
            Xs0[i] = g_Qp[0][qb0 + i] + g_Qp[1][qb0 + i]
                   + g_Qp[2][qb0 + i] + g_Qp[3][qb0 + i];
        __syncthreads();     // also publishes mbar init
        // rows gid, 8+gid, 16+gid x cols (k*8+tig, +4): 6 unique u32/lane/k
        #pragma unroll
        for (int i = 0; i < 3; i++) {
            const int k = w * 3 + i;
            const int c0 = k * 8 + tig;
            const uint32_t q0 = f2tf(Xs0[gid * 96 + c0]);
            const uint32_t q1 = f2tf(Xs0[(8 + gid) * 96 + c0]);
            const uint32_t q2 = f2tf(Xs0[(16 + gid) * 96 + c0]);
            const uint32_t q3 = f2tf(Xs0[gid * 96 + c0 + 4]);
            const uint32_t q4 = f2tf(Xs0[(8 + gid) * 96 + c0 + 4]);
            const uint32_t q5 = f2tf(Xs0[(16 + gid) * 96 + c0 + 4]);
            qA[k * 32 + lane] = make_uint4(q0, q1, q3, q4);
            qB[k * 32 + lane] = make_uint2(q2, q5);
        }
        if (t == 0) {                      // expect for prologue loads
            mbar_expect(mbarA, TILE_BYTES_TX);
            mbar_expect(mbarB, TILE_BYTES_TX);
        }
        __syncthreads();                   // frags + expects visible; Xs0 free
    }

    float Oacc[2][3][4];            // [mtile][c-tile][frag]
    float Lp[3] = {0.f, 0.f, 0.f};  // exp sums: hm = gid, 8+gid, 16+gid
    #pragma unroll
    for (int a = 0; a < 2; a++)
        #pragma unroll
        for (int ct = 0; ct < 3; ct++)
            #pragma unroll
            for (int i = 0; i < 4; i++) Oacc[a][ct][i] = 0.f;

    const float* xb = x + (size_t)b * CHN * HWN;
    const int n0 = split * CHUNK;
    const int n0w = 16 * w;      // GEMM1: warp's n-quarter
    const int c0w = 24 * w;      // GEMM2: warp's c-quarter

    // bulk tile loader: threads 0..95 issue one 256B row each
    auto bulk_load = [&](int buf, int tile, uint32_t mbar) {
        if (t < CHN) {
            const int base = n0 + tile * TN;
            const uint32_t dst = sbase + (uint32_t)(buf * XS_FLOATS + t * TNP) * 4;
            cp_bulk(dst, xb + (size_t)t * HWN + base, TN * 4, mbar);
        }
    };

    // exp + store + L for one tile's score frags
    auto expStore = [&](float c4[2][2][4], float* Ps) {
        #pragma unroll
        for (int nt = 0; nt < 2; nt++) {
            const int col = n0w + nt * 8 + 2 * tig;
            {
                const float p0 = __uint_as_float(f2tf(__expf(c4[0][nt][0])));
                const float p1 = __uint_as_float(f2tf(__expf(c4[0][nt][1])));
                Ps[gid * TNP + col] = p0; Ps[gid * TNP + col + 1] = p1;
                Lp[0] += p0 + p1;
            }
            {
                const float p0 = __uint_as_float(f2tf(__expf(c4[0][nt][2])));
                const float p1 = __uint_as_float(f2tf(__expf(c4[0][nt][3])));
                Ps[(8 + gid) * TNP + col] = p0; Ps[(8 + gid) * TNP + col + 1] = p1;
                Lp[1] += p0 + p1;
            }
            {
                const float p0 = __uint_as_float(f2tf(__expf(c4[1][nt][2])));
                const float p1 = __uint_as_float(f2tf(__expf(c4[1][nt][3])));
                Ps[(16 + gid) * TNP + col] = p0; Ps[(16 + gid) * TNP + col + 1] = p1;
                Lp[2] += p0 + p1;
            }
        }
    };

    // GEMM2 for one tile: Oacc += P[24 x 64] @ X^T (warp's c-quarter)
    auto gemm2 = [&](const float* Xs, const float* Ps) {
        #pragma unroll
        for (int k = 0; k < 8; k++) {
            const int nc = k * 8 + tig;
            const uint32_t pa0 = __float_as_uint(Ps[gid * TNP + nc]);
            const uint32_t pa1 = __float_as_uint(Ps[(8 + gid) * TNP + nc]);
            const uint32_t pa2 = __float_as_uint(Ps[gid * TNP + nc + 4]);
            const uint32_t pa3 = __float_as_uint(Ps[(8 + gid) * TNP + nc + 4]);
            const uint32_t pb1 = __float_as_uint(Ps[(16 + gid) * TNP + nc]);
            const uint32_t pb3 = __float_as_uint(Ps[(16 + gid) * TNP + nc + 4]);
            #pragma unroll
            for (int ct = 0; ct < 3; ct++) {
                const int crow = c0w + ct * 8 + gid;
                const uint32_t b0 = f2tf(Xs[crow * TNP + nc]);
                const uint32_t b1 = f2tf(Xs[crow * TNP + nc + 4]);
                mma8(Oacc[0][ct], pa0, pa1, pa2, pa3, b0, b1);   // rows 0-15
                mma8(Oacc[1][ct], pa1, pb1, pa3, pb3, b0, b1);   // rows 8-23
            }
        }
    };

    bulk_load(0, 0, mbarA);
    bulk_load(1, 1, mbarB);

    uint32_t phase = 0;
    for (int r = 0; r < NPAIRS; r++) {
        const float* XsA = Xs0;
        const float* XsB = Xs0 + XS_FLOATS;

        mbar_wait(mbarA, phase);
        mbar_wait(mbarB, phase);
        if (t == 0 && r + 1 < NPAIRS) {      // expect for NEXT phase's loads
            mbar_expect(mbarA, TILE_BYTES_TX);
            mbar_expect(mbarB, TILE_BYTES_TX);
        }
        __syncthreads();     // all past waits; expects ordered before issues

        // ---- GEMM1 over both tiles: Q frags loaded once per k ----
        float cA[2][2][4], cB[2][2][4];
        #pragma unroll
        for (int a = 0; a < 2; a++)
            #pragma unroll
            for (int nt = 0; nt < 2; nt++)
                #pragma unroll
                for (int i = 0; i < 4; i++) { cA[a][nt][i] = 0.f; cB[a][nt][i] = 0.f; }

        #pragma unroll
        for (int k = 0; k < 12; k++) {
            const uint4 fa = qA[k * 32 + lane];
            const uint2 fb = qB[k * 32 + lane];
            // af0 = {fa.x, fa.y, fa.z, fa.w}; af1 = {fa.y, fb.x, fa.w, fb.y}
            #pragma unroll
            for (int nt = 0; nt < 2; nt++) {
                const int ncol = n0w + nt * 8 + gid;
                const int r0 = (k * 8 + tig) * TNP + ncol;
                const int r1 = (k * 8 + tig + 4) * TNP + ncol;
                {
                    const uint32_t b0 = f2tf(XsA[r0]);
                    const uint32_t b1 = f2tf(XsA[r1]);
                    mma8(cA[0][nt], fa.x, fa.y, fa.z, fa.w, b0, b1);
                    mma8(cA[1][nt], fa.y, fb.x, fa.w, fb.y, b0, b1);
                }
                {
                    const uint32_t b0 = f2tf(XsB[r0]);
                    const uint32_t b1 = f2tf(XsB[r1]);
                    mma8(cB[0][nt], fa.x, fa.y, fa.z, fa.w, b0, b1);
                    mma8(cB[1][nt], fa.y, fb.x, fa.w, fb.y, b0, b1);
                }
            }
        }

        expStore(cA, PsA);
        expStore(cB, PsB);
        __syncthreads();     // Ps visible to all warps

        // ---- GEMM2 tile A; free bufA; refill via bulk DMA ----
        gemm2(XsA, PsA);
        __syncthreads();     // all warps done reading bufA
        if (r + 1 < NPAIRS) bulk_load(0, 2 * r + 2, mbarA);

        // ---- GEMM2 tile B; free bufB; refill ----
        gemm2(XsB, PsB);
        __syncthreads();     // all warps done reading bufB (and PsA/PsB)
        if (r + 1 < NPAIRS) bulk_load(1, 2 * r + 3, mbarB);

        phase ^= 1;
    }

    // ---- epilogue: each warp owns hm 0..23 x its 24 c columns ----
    const size_t outbase = (size_t)(b * NSPLIT + split) * (NHM * CHN);
    #pragma unroll
    for (int ct = 0; ct < 3; ct++) {
        const int col = c0w + ct * 8 + 2 * tig;
        g_accP[outbase + gid * CHN + col]            = Oacc[0][ct][0];
        g_accP[outbase + gid * CHN + col + 1]        = Oacc[0][ct][1];
        g_accP[outbase + (8 + gid) * CHN + col]      = Oacc[0][ct][2];
        g_accP[outbase + (8 + gid) * CHN + col + 1]  = Oacc[0][ct][3];
        g_accP[outbase + (16 + gid) * CHN + col]     = Oacc[1][ct][2];
        g_accP[outbase + (16 + gid) * CHN + col + 1] = Oacc[1][ct][3];
    }

    // ---- L reduction: sum over tig lanes, then over the 4 warps ----
    #pragma unroll
    for (int i = 0; i < 3; i++) {
        float v = Lp[i];
        v += __shfl_xor_sync(0xffffffffu, v, 1);
        v += __shfl_xor_sync(0xffffffffu, v, 2);
        Lp[i] = v;
    }
    if (tig == 0) {
        Lred[w * 24 + gid]      = Lp[0];
        Lred[w * 24 + 8 + gid]  = Lp[1];
        Lred[w * 24 + 16 + gid] = Lp[2];
    }
    __syncthreads();
    if (t < NHM) {
        g_LP[(b * NSPLIT + split) * NHM + t] =
            Lred[t] + Lred[24 + t] + Lred[48 + t] + Lred[72 + t];
    }
}

// ---------------------------------------------------------------------------
// Kernel 3: combine split partials -> g_O[b][m][h*96+c] = (sum_s acc)/(sum_s L)
// ---------------------------------------------------------------------------
__global__ __launch_bounds__(256)
void combine_kernel() {
    const int i = blockIdx.x * 256 + threadIdx.x;   // 0 .. 147455
    const int b = i / (NHM * CHN);
    const int r = i % (NHM * CHN);
    const int hm = r / CHN, c = r % CHN;
    float a = 0.f, L = 0.f;
    #pragma unroll
    for (int s = 0; s < NSPLIT; s++) {
        a += g_accP[(size_t)(b * NSPLIT + s) * (NHM * CHN) + r];
        L += g_LP[(b * NSPLIT + s) * NHM + hm];
    }
    const int h = hm / 6, m = hm % 6;
    g_O[(size_t)b * 2304 + m * 384 + h * CHN + c] = a / L;
}

// ---------------------------------------------------------------------------
// Kernel 4: output projection + residual (d = t % 192; NOT a bitmask).
// ---------------------------------------------------------------------------
__global__ __launch_bounds__(384)
void proj_kernel(const float* __restrict__ z,
                 const float* __restrict__ Wo,
                 const float* __restrict__ bo,
                 float* __restrict__ out) {
    __shared__ float outRow[6 * 384];
    __shared__ float part[192 * 6];
    const int b = blockIdx.x;
    const int t = threadIdx.x;
    const int d = t % 192;

    for (int i = t; i < 2304; i += 384) outRow[i] = g_O[(size_t)b * 2304 + i];
    __syncthreads();

    const int j0 = (t >= 192) ? 192 : 0;
    float accm[6] = {0.f, 0.f, 0.f, 0.f, 0.f, 0.f};
    #pragma unroll 16
    for (int jj = 0; jj < 192; jj++) {
        const int j = j0 + jj;
        const float w = Wo[j * 192 + d];
        #pragma unroll
        for (int m = 0; m < 6; m++) accm[m] += outRow[m * 384 + j] * w;
    }
    if (t >= 192) {
        #pragma unroll
        for (int m = 0; m < 6; m++) part[d * 6 + m] = accm[m];
    }
    __syncthreads();
    if (t < 192) {
        const float bod = bo[d];
        #pragma unroll
        for (int m = 0; m < 6; m++)
            out[((size_t)b * 6 + m) * 192 + d] =
                z[((size_t)b * 6 + m) * 192 + d] + accm[m] + part[d * 6 + m] + bod;
    }
}

// ---------------------------------------------------------------------------
extern "C" void kernel_launch(void* const* d_in, const int* in_sizes, int n_in,
                              void* d_out, int out_size) {
    const float* x  = (const float*)d_in[0];
    const float* z  = (const float*)d_in[1];
    const float* Wq = (const float*)d_in[2];
    const float* bq = (const float*)d_in[3];
    const float* Wo = (const float*)d_in[4];
    const float* bo = (const float*)d_in[5];
    float* out = (float*)d_out;

    cudaFuncSetAttribute(attn_kernel,
                         cudaFuncAttributeMaxDynamicSharedMemorySize, SMEM2_BYTES);

    prof_marker<<<1, 32>>>();                                   // idx 0
    qproj_kernel<<<dim3(BATCH, QSPLIT), 384>>>(z, Wq, bq);      // idx 1
    prof_marker<<<1, 32>>>();                                   // idx 2
    attn_kernel<<<dim3(NSPLIT, BATCH), THREADS2, SMEM2_BYTES>>>(x);  // idx 3 (ncu)
    combine_kernel<<<576, 256>>>();                             // idx 4
    proj_kernel<<<BATCH, 384>>>(z, Wo, bo, out);                // idx 5
}

// round 16
// speedup vs baseline: 1.0606x; 1.0571x over previous
#include <cuda_runtime.h>
#include <cuda_bf16.h>
#include <cstdint>

// ---------------------------------------------------------------------------
// Mobile2Former cross-attention, single-pass streaming softmax (scores bounded
// |s| < ~2; softmax shift-invariant so no max subtraction needed).
//
//   x : (64, 96, 112, 112) fp32 -> xf (b, n=12544, c=96), K = V = xf
//   q = SCALE * (z @ Wq + bq); p = exp(q.xf); out = (p@xf)/sum(p)
//   y = z + out @ Wo + bo
//
// Launch order: marker, qproj, marker, attn, final
//   (ncu captures absolute launch index 3 -> attn)
//
// R16 = R13 attn FROZEN (best: 97.2us) + non-attn overhead reduction:
//   - qproj K-split 4 -> 8 (halved serial load chain)
//   - combine+proj fused into one kernel (one launch + no g_O round-trip)
// ---------------------------------------------------------------------------

#define BATCH   64
#define CHN     96
#define HWN     12544
#define NSPLIT  14
#define CHUNK   896
#define NHM     24
#define TN      64
#define TNP     68             // padded row stride (floats)
#define NTILES  14
#define NPAIRS  7
#define THREADS2 128
#define XS_FLOATS (CHN * TNP)                 // 6528 per buffer
#define PS_FLOATS (NHM * TNP)                 // 1632 per tile
#define QA_U32   (12 * 32 * 4)                // 1536
#define QB_U32   (12 * 32 * 2)                // 768
#define SMEM2_FLOATS (2*XS_FLOATS + 2*PS_FLOATS + QA_U32 + QB_U32 + 96)  // 18720
#define SMEM2_BYTES  (SMEM2_FLOATS * 4)       // 74880 B (3 CTAs/SM)
#define SCALE_F 0.10206207261596575f          // 96^-0.5
#define QSPLIT  8

__device__ float g_Qp[QSPLIT][BATCH * NHM * CHN];        // K-split q partials
__device__ float g_accP[BATCH * NSPLIT * NHM * CHN];     // split numerators
__device__ float g_LP[BATCH * NSPLIT * NHM];             // split denominators

// ---- tf32 helpers ----
__device__ __forceinline__ uint32_t f2tf(float f) {
    uint32_t u;
    asm("cvt.rna.tf32.f32 %0, %1;" : "=r"(u) : "f"(f));
    return u;
}
__device__ __forceinline__ void mma8(float* c,
                                     uint32_t a0, uint32_t a1, uint32_t a2, uint32_t a3,
                                     uint32_t b0, uint32_t b1) {
    asm("mma.sync.aligned.m16n8k8.row.col.f32.tf32.tf32.f32 "
        "{%0,%1,%2,%3}, {%4,%5,%6,%7}, {%8,%9}, {%0,%1,%2,%3};"
        : "+f"(c[0]), "+f"(c[1]), "+f"(c[2]), "+f"(c[3])
        : "r"(a0), "r"(a1), "r"(a2), "r"(a3), "r"(b0), "r"(b1));
}
__device__ __forceinline__ void cp_async16(uint32_t dst, const float* src) {
    asm volatile("cp.async.cg.shared.global [%0], [%1], 16;" :: "r"(dst), "l"(src));
}

__global__ void prof_marker() {}

// ---------------------------------------------------------------------------
// Kernel 1: Q projection, grid (BATCH, 8): grid.y = K-eighth (24 d each).
// ---------------------------------------------------------------------------
__global__ __launch_bounds__(384)
void qproj_kernel(const float* __restrict__ z,
                  const float* __restrict__ Wq,
                  const float* __restrict__ bq) {
    __shared__ float zs[6 * 192];
    const int b = blockIdx.x;
    const int part = blockIdx.y;
    const int j = threadIdx.x;
    for (int i = j; i < 6 * 192; i += 384) zs[i] = z[b * 6 * 192 + i];
    __syncthreads();

    const int d0 = 24 * part;
    float acc[6] = {0.f, 0.f, 0.f, 0.f, 0.f, 0.f};
    #pragma unroll 24
    for (int dd = 0; dd < 24; dd++) {
        const float w = Wq[(d0 + dd) * 384 + j];
        #pragma unroll
        for (int m = 0; m < 6; m++) acc[m] += zs[m * 192 + d0 + dd] * w;
    }
    const int h = j / CHN, c = j % CHN;
    const float bias = (part == 0) ? bq[j] : 0.f;
    #pragma unroll
    for (int m = 0; m < 6; m++)
        g_Qp[part][(size_t)b * (NHM * CHN) + (h * 6 + m) * CHN + c] =
            (acc[m] + bias) * SCALE_F;
}

// ---------------------------------------------------------------------------
// Kernel 2: streaming attention (R13 FROZEN, except 8-way Q partial sum).
// ---------------------------------------------------------------------------
__global__ __launch_bounds__(THREADS2, 3)
void attn_kernel(const float* __restrict__ x) {
    extern __shared__ float sm[];
    float*    Xs0  = sm;                                   // [2][96][68]
    float*    PsA  = sm + 2 * XS_FLOATS;                   // [24][68]
    float*    PsB  = PsA + PS_FLOATS;                      // [24][68]
    uint4*    qA   = (uint4*)(PsB + PS_FLOATS);            // [12][32]
    uint2*    qB   = (uint2*)((uint32_t*)qA + QA_U32);     // [12][32]
    float*    Lred = (float*)((uint32_t*)qA + QA_U32 + QB_U32);  // [4][24]

    const int t     = threadIdx.x;
    const int b     = blockIdx.y;
    const int split = blockIdx.x;
    const int lane  = t & 31;
    const int w     = t >> 5;
    const int gid   = lane >> 2;     // 0..7
    const int tig   = lane & 3;      // 0..3

    // ---- stage Q (coalesced) into Xs0, then build deduped tf32 fragments ----
    {
        const size_t qb0 = (size_t)b * (NHM * CHN);
        for (int i = t; i < NHM * CHN; i += THREADS2) {
            float v = 0.f;
            #pragma unroll
            for (int p = 0; p < QSPLIT; p++) v += g_Qp[p][qb0 + i];
            Xs0[i] = v;
        }
        __syncthreads();
        // rows gid, 8+gid, 16+gid x cols (k*8+tig, +4): 6 unique u32/lane/k
        #pragma unroll
        for (int i = 0; i < 3; i++) {
            const int k = w * 3 + i;
            const int c0 = k * 8 + tig;
            const uint32_t q0 = f2tf(Xs0[gid * 96 + c0]);
            const uint32_t q1 = f2tf(Xs0[(8 + gid) * 96 + c0]);
            const uint32_t q2 = f2tf(Xs0[(16 + gid) * 96 + c0]);
            const uint32_t q3 = f2tf(Xs0[gid * 96 + c0 + 4]);
            const uint32_t q4 = f2tf(Xs0[(8 + gid) * 96 + c0 + 4]);
            const uint32_t q5 = f2tf(Xs0[(16 + gid) * 96 + c0 + 4]);
            qA[k * 32 + lane] = make_uint4(q0, q1, q3, q4);
            qB[k * 32 + lane] = make_uint2(q2, q5);
        }
        __syncthreads();
    }

    float Oacc[2][3][4];            // [mtile][c-tile][frag]
    float Lp[3] = {0.f, 0.f, 0.f};  // exp sums: hm = gid, 8+gid, 16+gid
    #pragma unroll
    for (int a = 0; a < 2; a++)
        #pragma unroll
        for (int ct = 0; ct < 3; ct++)
            #pragma unroll
            for (int i = 0; i < 4; i++) Oacc[a][ct][i] = 0.f;

    const float* xb = x + (size_t)b * CHN * HWN;
    const int n0 = split * CHUNK;
    const int n0w = 16 * w;      // GEMM1: warp's n-quarter
    const int c0w = 24 * w;      // GEMM2: warp's c-quarter

    auto prefetch = [&](int buf, int tile) {
        const int base = n0 + tile * TN;
        uint32_t dst = (uint32_t)__cvta_generic_to_shared(Xs0 + buf * XS_FLOATS);
        #pragma unroll
        for (int kk = 0; kk < 12; kk++) {
            const int idx = kk * THREADS2 + t;
            const int c = idx >> 4, f4 = (idx & 15) << 2;
            cp_async16(dst + (uint32_t)(c * TNP + f4) * 4,
                       xb + (size_t)c * HWN + base + f4);
        }
        asm volatile("cp.async.commit_group;");
    };

    // exp + store + L for one tile's score frags
    auto expStore = [&](float c4[2][2][4], float* Ps) {
        #pragma unroll
        for (int nt = 0; nt < 2; nt++) {
            const int col = n0w + nt * 8 + 2 * tig;
            {
                const float p0 = __uint_as_float(f2tf(__expf(c4[0][nt][0])));
                const float p1 = __uint_as_float(f2tf(__expf(c4[0][nt][1])));
                Ps[gid * TNP + col] = p0; Ps[gid * TNP + col + 1] = p1;
                Lp[0] += p0 + p1;
            }
            {
                const float p0 = __uint_as_float(f2tf(__expf(c4[0][nt][2])));
                const float p1 = __uint_as_float(f2tf(__expf(c4[0][nt][3])));
                Ps[(8 + gid) * TNP + col] = p0; Ps[(8 + gid) * TNP + col + 1] = p1;
                Lp[1] += p0 + p1;
            }
            {
                const float p0 = __uint_as_float(f2tf(__expf(c4[1][nt][2])));
                const float p1 = __uint_as_float(f2tf(__expf(c4[1][nt][3])));
                Ps[(16 + gid) * TNP + col] = p0; Ps[(16 + gid) * TNP + col + 1] = p1;
                Lp[2] += p0 + p1;
            }
        }
    };

    // GEMM2 for one tile: Oacc += P[24 x 64] @ X^T (warp's c-quarter)
    auto gemm2 = [&](const float* Xs, const float* Ps) {
        #pragma unroll
        for (int k = 0; k < 8; k++) {
            const int nc = k * 8 + tig;
            const uint32_t pa0 = __float_as_uint(Ps[gid * TNP + nc]);
            const uint32_t pa1 = __float_as_uint(Ps[(8 + gid) * TNP + nc]);
            const uint32_t pa2 = __float_as_uint(Ps[gid * TNP + nc + 4]);
            const uint32_t pa3 = __float_as_uint(Ps[(8 + gid) * TNP + nc + 4]);
            const uint32_t pb1 = __float_as_uint(Ps[(16 + gid) * TNP + nc]);
            const uint32_t pb3 = __float_as_uint(Ps[(16 + gid) * TNP + nc + 4]);
            #pragma unroll
            for (int ct = 0; ct < 3; ct++) {
                const int crow = c0w + ct * 8 + gid;
                const uint32_t b0 = f2tf(Xs[crow * TNP + nc]);
                const uint32_t b1 = f2tf(Xs[crow * TNP + nc + 4]);
                mma8(Oacc[0][ct], pa0, pa1, pa2, pa3, b0, b1);   // rows 0-15
                mma8(Oacc[1][ct], pa1, pb1, pa3, pb3, b0, b1);   // rows 8-23
            }
        }
    };

    prefetch(0, 0);
    prefetch(1, 1);

    for (int r = 0; r < NPAIRS; r++) {
        const float* XsA = Xs0;
        const float* XsB = Xs0 + XS_FLOATS;

        asm volatile("cp.async.wait_group 0;");   // both tiles of the pair
        __syncthreads();

        // ---- GEMM1 over both tiles: Q frags loaded once per k ----
        float cA[2][2][4], cB[2][2][4];
        #pragma unroll
        for (int a = 0; a < 2; a++)
            #pragma unroll
            for (int nt = 0; nt < 2; nt++)
                #pragma unroll
                for (int i = 0; i < 4; i++) { cA[a][nt][i] = 0.f; cB[a][nt][i] = 0.f; }

        #pragma unroll
        for (int k = 0; k < 12; k++) {
            const uint4 fa = qA[k * 32 + lane];
            const uint2 fb = qB[k * 32 + lane];
            // af0 = {fa.x, fa.y, fa.z, fa.w}; af1 = {fa.y, fb.x, fa.w, fb.y}
            #pragma unroll
            for (int nt = 0; nt < 2; nt++) {
                const int ncol = n0w + nt * 8 + gid;
                const int r0 = (k * 8 + tig) * TNP + ncol;
                const int r1 = (k * 8 + tig + 4) * TNP + ncol;
                {
                    const uint32_t b0 = f2tf(XsA[r0]);
                    const uint32_t b1 = f2tf(XsA[r1]);
                    mma8(cA[0][nt], fa.x, fa.y, fa.z, fa.w, b0, b1);
                    mma8(cA[1][nt], fa.y, fb.x, fa.w, fb.y, b0, b1);
                }
                {
                    const uint32_t b0 = f2tf(XsB[r0]);
                    const uint32_t b1 = f2tf(XsB[r1]);
                    mma8(cB[0][nt], fa.x, fa.y, fa.z, fa.w, b0, b1);
                    mma8(cB[1][nt], fa.y, fb.x, fa.w, fb.y, b0, b1);
                }
            }
        }

        expStore(cA, PsA);
        expStore(cB, PsB);
        __syncthreads();     // Ps visible to all warps

        // ---- GEMM2 tile A; free bufA; refill ----
        gemm2(XsA, PsA);
        __syncthreads();     // all warps done reading bufA
        if (r + 1 < NPAIRS) prefetch(0, 2 * r + 2);

        // ---- GEMM2 tile B; free bufB; refill ----
        gemm2(XsB, PsB);
        __syncthreads();     // all warps done reading bufB (and PsA/PsB)
        if (r + 1 < NPAIRS) prefetch(1, 2 * r + 3);
    }

    // ---- epilogue: each warp owns hm 0..23 x its 24 c columns ----
    const size_t outbase = (size_t)(b * NSPLIT + split) * (NHM * CHN);
    #pragma unroll
    for (int ct = 0; ct < 3; ct++) {
        const int col = c0w + ct * 8 + 2 * tig;
        g_accP[outbase + gid * CHN + col]            = Oacc[0][ct][0];
        g_accP[outbase + gid * CHN + col + 1]        = Oacc[0][ct][1];
        g_accP[outbase + (8 + gid) * CHN + col]      = Oacc[0][ct][2];
        g_accP[outbase + (8 + gid) * CHN + col + 1]  = Oacc[0][ct][3];
        g_accP[outbase + (16 + gid) * CHN + col]     = Oacc[1][ct][2];
        g_accP[outbase + (16 + gid) * CHN + col + 1] = Oacc[1][ct][3];
    }

    // ---- L reduction: sum over tig lanes, then over the 4 warps ----
    #pragma unroll
    for (int i = 0; i < 3; i++) {
        float v = Lp[i];
        v += __shfl_xor_sync(0xffffffffu, v, 1);
        v += __shfl_xor_sync(0xffffffffu, v, 2);
        Lp[i] = v;
    }
    if (tig == 0) {
        Lred[w * 24 + gid]      = Lp[0];
        Lred[w * 24 + 8 + gid]  = Lp[1];
        Lred[w * 24 + 16 + gid] = Lp[2];
    }
    __syncthreads();
    if (t < NHM) {
        g_LP[(b * NSPLIT + split) * NHM + t] =
            Lred[t] + Lred[24 + t] + Lred[48 + t] + Lred[72 + t];
    }
}

// ---------------------------------------------------------------------------
// Kernel 3 (fused): combine split partials + output projection + residual.
// grid 64 x block 384. Phase 1: 14-slot reduction -> smem outRow (MLP 14).
// Phase 2: proj (j0 K-split, smem staging). d = t % 192 (NOT a bitmask).
// ---------------------------------------------------------------------------
__global__ __launch_bounds__(384)
void final_kernel(const float* __restrict__ z,
                  const float* __restrict__ Wo,
                  const float* __restrict__ bo,
                  float* __restrict__ out) {
    __shared__ float outRow[6 * 384];   // [m][h*96+c]
    __shared__ float part[192 * 6];
    const int b = blockIdx.x;
    const int t = threadIdx.x;
    const int d = t % 192;

    // Phase 1: combine. One thread per (hm, c) x 6 iterations.
    for (int o = t; o < NHM * CHN; o += 384) {
        const int hm = o / CHN, c = o % CHN;
        float a = 0.f, L = 0.f;
        #pragma unroll
        for (int s = 0; s < NSPLIT; s++) {
            a += g_accP[(size_t)(b * NSPLIT + s) * (NHM * CHN) + o];
            L += g_LP[(b * NSPLIT + s) * NHM + hm];
        }
        const int h = hm / 6, m = hm % 6;
        outRow[m * 384 + h * CHN + c] = a / L;
    }
    __syncthreads();

    // Phase 2: projection + residual.
    const int j0 = (t >= 192) ? 192 : 0;
    float accm[6] = {0.f, 0.f, 0.f, 0.f, 0.f, 0.f};
    #pragma unroll 16
    for (int jj = 0; jj < 192; jj++) {
        const int j = j0 + jj;
        const float w = Wo[j * 192 + d];
        #pragma unroll
        for (int m = 0; m < 6; m++) accm[m] += outRow[m * 384 + j] * w;
    }
    if (t >= 192) {
        #pragma unroll
        for (int m = 0; m < 6; m++) part[d * 6 + m] = accm[m];
    }
    __syncthreads();
    if (t < 192) {
        const float bod = bo[d];
        #pragma unroll
        for (int m = 0; m < 6; m++)
            out[((size_t)b * 6 + m) * 192 + d] =
                z[((size_t)b * 6 + m) * 192 + d] + accm[m] + part[d * 6 + m] + bod;
    }
}

// ---------------------------------------------------------------------------
extern "C" void kernel_launch(void* const* d_in, const int* in_sizes, int n_in,
                              void* d_out, int out_size) {
    const float* x  = (const float*)d_in[0];
    const float* z  = (const float*)d_in[1];
    const float* Wq = (const float*)d_in[2];
    const float* bq = (const float*)d_in[3];
    const float* Wo = (const float*)d_in[4];
    const float* bo = (const float*)d_in[5];
    float* out = (float*)d_out;

    cudaFuncSetAttribute(attn_kernel,
                         cudaFuncAttributeMaxDynamicSharedMemorySize, SMEM2_BYTES);

    prof_marker<<<1, 32>>>();                                   // idx 0
    qproj_kernel<<<dim3(BATCH, QSPLIT), 384>>>(z, Wq, bq);      // idx 1
    prof_marker<<<1, 32>>>();                                   // idx 2
    attn_kernel<<<dim3(NSPLIT, BATCH), THREADS2, SMEM2_BYTES>>>(x);  // idx 3 (ncu)
    final_kernel<<<BATCH, 384>>>(z, Wo, bo, out);               // idx 4
}

// round 17
// speedup vs baseline: 1.0937x; 1.0312x over previous
#include <cuda_runtime.h>
#include <cuda_bf16.h>
#include <cstdint>

// ---------------------------------------------------------------------------
// Mobile2Former cross-attention, single-pass streaming softmax (scores bounded
// |s| < ~2; softmax shift-invariant so no max subtraction needed).
//
//   x : (64, 96, 112, 112) fp32 -> xf (b, n=12544, c=96), K = V = xf
//   q = SCALE * (z @ Wq + bq); p = exp(q.xf); out = (p@xf)/sum(p)
//   y = z + out @ Wo + bo
//
// Launch order: marker, qproj, marker, attn, combine, proj
//   (ncu captures absolute launch index 3 -> attn)
//
// R17 = R13 verbatim + ONE change: X (B-operand) tf32 CVTs removed — raw fp32
// bits are passed to mma.sync.tf32 (HW truncates to tf32; CUTLASS fast path).
// Removes ~192 ALU CVTs per warp-round. Q and P keep rounded tf32 (accuracy /
// numerator-denominator consistency). rel_err budget ~1e-4 (<1e-3 threshold).
// ---------------------------------------------------------------------------

#define BATCH   64
#define CHN     96
#define HWN     12544
#define NSPLIT  14
#define CHUNK   896
#define NHM     24
#define TN      64
#define TNP     68             // padded row stride (floats)
#define NTILES  14
#define NPAIRS  7
#define THREADS2 128
#define XS_FLOATS (CHN * TNP)                 // 6528 per buffer
#define PS_FLOATS (NHM * TNP)                 // 1632 per tile
#define QA_U32   (12 * 32 * 4)                // 1536
#define QB_U32   (12 * 32 * 2)                // 768
#define SMEM2_FLOATS (2*XS_FLOATS + 2*PS_FLOATS + QA_U32 + QB_U32 + 96)  // 18720
#define SMEM2_BYTES  (SMEM2_FLOATS * 4)       // 74880 B (3 CTAs/SM)
#define SCALE_F 0.10206207261596575f          // 96^-0.5
#define QSPLIT  4

__device__ float g_Qp[QSPLIT][BATCH * NHM * CHN];        // K-split q partials
__device__ float g_accP[BATCH * NSPLIT * NHM * CHN];     // split numerators
__device__ float g_LP[BATCH * NSPLIT * NHM];             // split denominators
__device__ float g_O[BATCH * 6 * 384];                   // attn out [b][m][h*96+c]

// ---- tf32 helpers ----
__device__ __forceinline__ uint32_t f2tf(float f) {
    uint32_t u;
    asm("cvt.rna.tf32.f32 %0, %1;" : "=r"(u) : "f"(f));
    return u;
}
__device__ __forceinline__ void mma8(float* c,
                                     uint32_t a0, uint32_t a1, uint32_t a2, uint32_t a3,
                                     uint32_t b0, uint32_t b1) {
    asm("mma.sync.aligned.m16n8k8.row.col.f32.tf32.tf32.f32 "
        "{%0,%1,%2,%3}, {%4,%5,%6,%7}, {%8,%9}, {%0,%1,%2,%3};"
        : "+f"(c[0]), "+f"(c[1]), "+f"(c[2]), "+f"(c[3])
        : "r"(a0), "r"(a1), "r"(a2), "r"(a3), "r"(b0), "r"(b1));
}
__device__ __forceinline__ void cp_async16(uint32_t dst, const float* src) {
    asm volatile("cp.async.cg.shared.global [%0], [%1], 16;" :: "r"(dst), "l"(src));
}

__global__ void prof_marker() {}

// ---------------------------------------------------------------------------
// Kernel 1: Q projection, grid (BATCH, 4): grid.y = K-quarter (48 d each).
// ---------------------------------------------------------------------------
__global__ __launch_bounds__(384)
void qproj_kernel(const float* __restrict__ z,
                  const float* __restrict__ Wq,
                  const float* __restrict__ bq) {
    __shared__ float zs[6 * 192];
    const int b = blockIdx.x;
    const int part = blockIdx.y;
    const int j = threadIdx.x;
    for (int i = j; i < 6 * 192; i += 384) zs[i] = z[b * 6 * 192 + i];
    __syncthreads();

    const int d0 = 48 * part;
    float acc[6] = {0.f, 0.f, 0.f, 0.f, 0.f, 0.f};
    #pragma unroll 16
    for (int dd = 0; dd < 48; dd++) {
        const float w = Wq[(d0 + dd) * 384 + j];
        #pragma unroll
        for (int m = 0; m < 6; m++) acc[m] += zs[m * 192 + d0 + dd] * w;
    }
    const int h = j / CHN, c = j % CHN;
    const float bias = (part == 0) ? bq[j] : 0.f;
    #pragma unroll
    for (int m = 0; m < 6; m++)
        g_Qp[part][(size_t)b * (NHM * CHN) + (h * 6 + m) * CHN + c] =
            (acc[m] + bias) * SCALE_F;
}

// ---------------------------------------------------------------------------
// Kernel 2: streaming attention, tf32 tensor cores, pair-processed tiles.
// ---------------------------------------------------------------------------
__global__ __launch_bounds__(THREADS2, 3)
void attn_kernel(const float* __restrict__ x) {
    extern __shared__ float sm[];
    float*    Xs0  = sm;                                   // [2][96][68]
    float*    PsA  = sm + 2 * XS_FLOATS;                   // [24][68]
    float*    PsB  = PsA + PS_FLOATS;                      // [24][68]
    uint4*    qA   = (uint4*)(PsB + PS_FLOATS);            // [12][32]
    uint2*    qB   = (uint2*)((uint32_t*)qA + QA_U32);     // [12][32]
    float*    Lred = (float*)((uint32_t*)qA + QA_U32 + QB_U32);  // [4][24]

    const int t     = threadIdx.x;
    const int b     = blockIdx.y;
    const int split = blockIdx.x;
    const int lane  = t & 31;
    const int w     = t >> 5;
    const int gid   = lane >> 2;     // 0..7
    const int tig   = lane & 3;      // 0..3

    // ---- stage Q (coalesced) into Xs0, then build deduped tf32 fragments ----
    {
        const size_t qb0 = (size_t)b * (NHM * CHN);
        for (int i = t; i < NHM * CHN; i += THREADS2)
            Xs0[i] = g_Qp[0][qb0 + i] + g_Qp[1][qb0 + i]
                   + g_Qp[2][qb0 + i] + g_Qp[3][qb0 + i];
        __syncthreads();
        // rows gid, 8+gid, 16+gid x cols (k*8+tig, +4): 6 unique u32/lane/k
        #pragma unroll
        for (int i = 0; i < 3; i++) {
            const int k = w * 3 + i;
            const int c0 = k * 8 + tig;
            const uint32_t q0 = f2tf(Xs0[gid * 96 + c0]);
            const uint32_t q1 = f2tf(Xs0[(8 + gid) * 96 + c0]);
            const uint32_t q2 = f2tf(Xs0[(16 + gid) * 96 + c0]);
            const uint32_t q3 = f2tf(Xs0[gid * 96 + c0 + 4]);
            const uint32_t q4 = f2tf(Xs0[(8 + gid) * 96 + c0 + 4]);
            const uint32_t q5 = f2tf(Xs0[(16 + gid) * 96 + c0 + 4]);
            qA[k * 32 + lane] = make_uint4(q0, q1, q3, q4);
            qB[k * 32 + lane] = make_uint2(q2, q5);
        }
        __syncthreads();
    }

    float Oacc[2][3][4];            // [mtile][c-tile][frag]
    float Lp[3] = {0.f, 0.f, 0.f};  // exp sums: hm = gid, 8+gid, 16+gid
    #pragma unroll
    for (int a = 0; a < 2; a++)
        #pragma unroll
        for (int ct = 0; ct < 3; ct++)
            #pragma unroll
            for (int i = 0; i < 4; i++) Oacc[a][ct][i] = 0.f;

    const float* xb = x + (size_t)b * CHN * HWN;
    const int n0 = split * CHUNK;
    const int n0w = 16 * w;      // GEMM1: warp's n-quarter
    const int c0w = 24 * w;      // GEMM2: warp's c-quarter

    auto prefetch = [&](int buf, int tile) {
        const int base = n0 + tile * TN;
        uint32_t dst = (uint32_t)__cvta_generic_to_shared(Xs0 + buf * XS_FLOATS);
        #pragma unroll
        for (int kk = 0; kk < 12; kk++) {
            const int idx = kk * THREADS2 + t;
            const int c = idx >> 4, f4 = (idx & 15) << 2;
            cp_async16(dst + (uint32_t)(c * TNP + f4) * 4,
                       xb + (size_t)c * HWN + base + f4);
        }
        asm volatile("cp.async.commit_group;");
    };

    // exp + store + L for one tile's score frags (P kept tf32-rounded so the
    // GEMM2 numerator matches the L denominator)
    auto expStore = [&](float c4[2][2][4], float* Ps) {
        #pragma unroll
        for (int nt = 0; nt < 2; nt++) {
            const int col = n0w + nt * 8 + 2 * tig;
            {
                const float p0 = __uint_as_float(f2tf(__expf(c4[0][nt][0])));
                const float p1 = __uint_as_float(f2tf(__expf(c4[0][nt][1])));
                Ps[gid * TNP + col] = p0; Ps[gid * TNP + col + 1] = p1;
                Lp[0] += p0 + p1;
            }
            {
                const float p0 = __uint_as_float(f2tf(__expf(c4[0][nt][2])));
                const float p1 = __uint_as_float(f2tf(__expf(c4[0][nt][3])));
                Ps[(8 + gid) * TNP + col] = p0; Ps[(8 + gid) * TNP + col + 1] = p1;
                Lp[1] += p0 + p1;
            }
            {
                const float p0 = __uint_as_float(f2tf(__expf(c4[1][nt][2])));
                const float p1 = __uint_as_float(f2tf(__expf(c4[1][nt][3])));
                Ps[(16 + gid) * TNP + col] = p0; Ps[(16 + gid) * TNP + col + 1] = p1;
                Lp[2] += p0 + p1;
            }
        }
    };

    // GEMM2 for one tile: Oacc += P[24 x 64] @ X^T (warp's c-quarter).
    // X passed as raw fp32 bits (HW truncates to tf32).
    auto gemm2 = [&](const float* Xs, const float* Ps) {
        #pragma unroll
        for (int k = 0; k < 8; k++) {
            const int nc = k * 8 + tig;
            const uint32_t pa0 = __float_as_uint(Ps[gid * TNP + nc]);
            const uint32_t pa1 = __float_as_uint(Ps[(8 + gid) * TNP + nc]);
            const uint32_t pa2 = __float_as_uint(Ps[gid * TNP + nc + 4]);
            const uint32_t pa3 = __float_as_uint(Ps[(8 + gid) * TNP + nc + 4]);
            const uint32_t pb1 = __float_as_uint(Ps[(16 + gid) * TNP + nc]);
            const uint32_t pb3 = __float_as_uint(Ps[(16 + gid) * TNP + nc + 4]);
            #pragma unroll
            for (int ct = 0; ct < 3; ct++) {
                const int crow = c0w + ct * 8 + gid;
                const uint32_t b0 = __float_as_uint(Xs[crow * TNP + nc]);      // no CVT
                const uint32_t b1 = __float_as_uint(Xs[crow * TNP + nc + 4]);  // no CVT
                mma8(Oacc[0][ct], pa0, pa1, pa2, pa3, b0, b1);   // rows 0-15
                mma8(Oacc[1][ct], pa1, pb1, pa3, pb3, b0, b1);   // rows 8-23
            }
        }
    };

    prefetch(0, 0);
    prefetch(1, 1);

    for (int r = 0; r < NPAIRS; r++) {
        const float* XsA = Xs0;
        const float* XsB = Xs0 + XS_FLOATS;

        asm volatile("cp.async.wait_group 0;");   // both tiles of the pair
        __syncthreads();

        // ---- GEMM1 over both tiles: Q frags loaded once per k ----
        float cA[2][2][4], cB[2][2][4];
        #pragma unroll
        for (int a = 0; a < 2; a++)
            #pragma unroll
            for (int nt = 0; nt < 2; nt++)
                #pragma unroll
                for (int i = 0; i < 4; i++) { cA[a][nt][i] = 0.f; cB[a][nt][i] = 0.f; }

        #pragma unroll
        for (int k = 0; k < 12; k++) {
            const uint4 fa = qA[k * 32 + lane];
            const uint2 fb = qB[k * 32 + lane];
            // af0 = {fa.x, fa.y, fa.z, fa.w}; af1 = {fa.y, fb.x, fa.w, fb.y}
            #pragma unroll
            for (int nt = 0; nt < 2; nt++) {
                const int ncol = n0w + nt * 8 + gid;
                const int r0 = (k * 8 + tig) * TNP + ncol;
                const int r1 = (k * 8 + tig + 4) * TNP + ncol;
                {
                    const uint32_t b0 = __float_as_uint(XsA[r0]);   // no CVT
                    const uint32_t b1 = __float_as_uint(XsA[r1]);   // no CVT
                    mma8(cA[0][nt], fa.x, fa.y, fa.z, fa.w, b0, b1);
                    mma8(cA[1][nt], fa.y, fb.x, fa.w, fb.y, b0, b1);
                }
                {
                    const uint32_t b0 = __float_as_uint(XsB[r0]);   // no CVT
                    const uint32_t b1 = __float_as_uint(XsB[r1]);   // no CVT
                    mma8(cB[0][nt], fa.x, fa.y, fa.z, fa.w, b0, b1);
                    mma8(cB[1][nt], fa.y, fb.x, fa.w, fb.y, b0, b1);
                }
            }
        }

        expStore(cA, PsA);
        expStore(cB, PsB);
        __syncthreads();     // Ps visible to all warps

        // ---- GEMM2 tile A; free bufA; refill ----
        gemm2(XsA, PsA);
        __syncthreads();     // all warps done reading bufA
        if (r + 1 < NPAIRS) prefetch(0, 2 * r + 2);

        // ---- GEMM2 tile B; free bufB; refill ----
        gemm2(XsB, PsB);
        __syncthreads();     // all warps done reading bufB (and PsA/PsB)
        if (r + 1 < NPAIRS) prefetch(1, 2 * r + 3);
    }

    // ---- epilogue: each warp owns hm 0..23 x its 24 c columns ----
    const size_t outbase = (size_t)(b * NSPLIT + split) * (NHM * CHN);
    #pragma unroll
    for (int ct = 0; ct < 3; ct++) {
        const int col = c0w + ct * 8 + 2 * tig;
        g_accP[outbase + gid * CHN + col]            = Oacc[0][ct][0];
        g_accP[outbase + gid * CHN + col + 1]        = Oacc[0][ct][1];
        g_accP[outbase + (8 + gid) * CHN + col]      = Oacc[0][ct][2];
        g_accP[outbase + (8 + gid) * CHN + col + 1]  = Oacc[0][ct][3];
        g_accP[outbase + (16 + gid) * CHN + col]     = Oacc[1][ct][2];
        g_accP[outbase + (16 + gid) * CHN + col + 1] = Oacc[1][ct][3];
    }

    // ---- L reduction: sum over tig lanes, then over the 4 warps ----
    #pragma unroll
    for (int i = 0; i < 3; i++) {
        float v = Lp[i];
        v += __shfl_xor_sync(0xffffffffu, v, 1);
        v += __shfl_xor_sync(0xffffffffu, v, 2);
        Lp[i] = v;
    }
    if (tig == 0) {
        Lred[w * 24 + gid]      = Lp[0];
        Lred[w * 24 + 8 + gid]  = Lp[1];
        Lred[w * 24 + 16 + gid] = Lp[2];
    }
    __syncthreads();
    if (t < NHM) {
        g_LP[(b * NSPLIT + split) * NHM + t] =
            Lred[t] + Lred[24 + t] + Lred[48 + t] + Lred[72 + t];
    }
}

// ---------------------------------------------------------------------------
// Kernel 3: combine split partials -> g_O[b][m][h*96+c] = (sum_s acc)/(sum_s L)
// ---------------------------------------------------------------------------
__global__ __launch_bounds__(256)
void combine_kernel() {
    const int i = blockIdx.x * 256 + threadIdx.x;   // 0 .. 147455
    const int b = i / (NHM * CHN);
    const int r = i % (NHM * CHN);
    const int hm = r / CHN, c = r % CHN;
    float a = 0.f, L = 0.f;
    #pragma unroll
    for (int s = 0; s < NSPLIT; s++) {
        a += g_accP[(size_t)(b * NSPLIT + s) * (NHM * CHN) + r];
        L += g_LP[(b * NSPLIT + s) * NHM + hm];
    }
    const int h = hm / 6, m = hm % 6;
    g_O[(size_t)b * 2304 + m * 384 + h * CHN + c] = a / L;
}

// ---------------------------------------------------------------------------
// Kernel 4: output projection + residual (d = t % 192; NOT a bitmask).
// ---------------------------------------------------------------------------
__global__ __launch_bounds__(384)
void proj_kernel(const float* __restrict__ z,
                 const float* __restrict__ Wo,
                 const float* __restrict__ bo,
                 float* __restrict__ out) {
    __shared__ float outRow[6 * 384];
    __shared__ float part[192 * 6];
    const int b = blockIdx.x;
    const int t = threadIdx.x;
    const int d = t % 192;

    for (int i = t; i < 2304; i += 384) outRow[i] = g_O[(size_t)b * 2304 + i];
    __syncthreads();

    const int j0 = (t >= 192) ? 192 : 0;
    float accm[6] = {0.f, 0.f, 0.f, 0.f, 0.f, 0.f};
    #pragma unroll 16
    for (int jj = 0; jj < 192; jj++) {
        const int j = j0 + jj;
        const float w = Wo[j * 192 + d];
        #pragma unroll
        for (int m = 0; m < 6; m++) accm[m] += outRow[m * 384 + j] * w;
    }
    if (t >= 192) {
        #pragma unroll
        for (int m = 0; m < 6; m++) part[d * 6 + m] = accm[m];
    }
    __syncthreads();
    if (t < 192) {
        const float bod = bo[d];
        #pragma unroll
        for (int m = 0; m < 6; m++)
            out[((size_t)b * 6 + m) * 192 + d] =
                z[((size_t)b * 6 + m) * 192 + d] + accm[m] + part[d * 6 + m] + bod;
    }
}

// ---------------------------------------------------------------------------
extern "C" void kernel_launch(void* const* d_in, const int* in_sizes, int n_in,
                              void* d_out, int out_size) {
    const float* x  = (const float*)d_in[0];
    const float* z  = (const float*)d_in[1];
    const float* Wq = (const float*)d_in[2];
    const float* bq = (const float*)d_in[3];
    const float* Wo = (const float*)d_in[4];
    const float* bo = (const float*)d_in[5];
    float* out = (float*)d_out;

    cudaFuncSetAttribute(attn_kernel,
                         cudaFuncAttributeMaxDynamicSharedMemorySize, SMEM2_BYTES);

    prof_marker<<<1, 32>>>();                                   // idx 0
    qproj_kernel<<<dim3(BATCH, QSPLIT), 384>>>(z, Wq, bq);      // idx 1
    prof_marker<<<1, 32>>>();                                   // idx 2
    attn_kernel<<<dim3(NSPLIT, BATCH), THREADS2, SMEM2_BYTES>>>(x);  // idx 3 (ncu)
    combine_kernel<<<576, 256>>>();                             // idx 4
    proj_kernel<<<BATCH, 384>>>(z, Wo, bo, out);                // idx 5
}